// round 8
// baseline (speedup 1.0000x reference)
#include <cuda_runtime.h>
#include <cuda_bf16.h>

#define BATCH 512
#define NIN   64
#define ADIM  64

typedef unsigned long long ull;

// ---------------- device scratch (static, no allocation) -------------------
__device__ uint4 g_Q4[248 * 512];        // quads(240)+triples(8), bf16, chunk layout:
                                         //   mat*512 + q*64 + row ; uint4 = row's k=8q..8q+7

#define AST4 17                          // A row stride in float4 units (68 floats)

// smem layout (floats): W0A | W1B | W2A | W3B | PaA | PbB | expa[4][64]
#define OFF_W0A 0
#define OFF_W1B 4352
#define OFF_W2A 8448
#define OFF_W3B 12800
#define OFF_PAA 16896
#define OFF_PBB 21248
#define OFF_EXPA 25344
#define SMEM_FLOATS (25344 + 256)
#define SMEM_BYTES (SMEM_FLOATS * 4)

// ---- packed f32x2 helpers (sm_103a) ---------------------------------------
__device__ __forceinline__ void ffma2(ull& d, ull a, ull b) {
    asm("fma.rn.f32x2 %0, %1, %2, %0;" : "+l"(d) : "l"(a), "l"(b));
}
__device__ __forceinline__ ull pk2(float x, float y) {
    ull r; asm("mov.b64 %0, {%1, %2};" : "=l"(r) : "f"(x), "f"(y)); return r;
}
__device__ __forceinline__ void up2(ull v, float& x, float& y) {
    asm("mov.b64 {%0, %1}, %2;" : "=f"(x), "=f"(y) : "l"(v));
}

__device__ __forceinline__ float sigc(float t, int c) {
    float s = __fdividef(1.0f, 1.0f + __expf(-t));
    return c ? s : 1.0f - s;
}

// warp-collective softmax of u[i][0..63] into dst[0..63]
__device__ __forceinline__ void warp_softmax(const float* __restrict__ u, int i,
                                             float* dst, int lane) {
    float u0 = u[i * 64 + lane], u1 = u[i * 64 + 32 + lane];
    float mm = fmaxf(u0, u1);
    #pragma unroll
    for (int o = 16; o; o >>= 1) mm = fmaxf(mm, __shfl_xor_sync(0xffffffffu, mm, o));
    float ss = __expf(u0 - mm) + __expf(u1 - mm);
    #pragma unroll
    for (int o = 16; o; o >>= 1) ss += __shfl_xor_sync(0xffffffffu, ss, o);
    float lse = mm + __logf(ss);
    dst[lane]      = __expf(u0 - lse);
    dst[lane + 32] = __expf(u1 - lse);
}

// Build W_i^c = sigmoid_c(theta_i) * expa into A-padded layout (stride AST4 f4)
__device__ __forceinline__ void buildW_A(const float4* __restrict__ th4, int i, int c,
                                         const float* expa, float4* dstA, int tid) {
    #pragma unroll
    for (int r = 0; r < 2; ++r) {
        int idx4 = tid + 512 * r;
        int row = idx4 >> 4, q = idx4 & 15, k0 = q * 4;
        float4 t4 = th4[i * 1024 + idx4];
        float4 o;
        o.x = sigc(t4.x, c) * expa[k0 + 0];
        o.y = sigc(t4.y, c) * expa[k0 + 1];
        o.z = sigc(t4.z, c) * expa[k0 + 2];
        o.w = sigc(t4.w, c) * expa[k0 + 3];
        dstA[row * AST4 + q] = o;
    }
}
// Same, into B row-major layout (16 f4 per row)
__device__ __forceinline__ void buildW_B(const float4* __restrict__ th4, int i, int c,
                                         const float* expa, float4* dstB, int tid) {
    #pragma unroll
    for (int r = 0; r < 2; ++r) {
        int idx4 = tid + 512 * r;
        int k0 = (idx4 & 15) * 4;
        float4 t4 = th4[i * 1024 + idx4];
        float4 o;
        o.x = sigc(t4.x, c) * expa[k0 + 0];
        o.y = sigc(t4.y, c) * expa[k0 + 1];
        o.z = sigc(t4.z, c) * expa[k0 + 2];
        o.w = sigc(t4.w, c) * expa[k0 + 3];
        dstB[idx4] = o;
    }
}

// 256-thread GEMM: C[a][seg*16 .. +15] = sum_j A[a][j]*B[j][cols], 16 accs (8 u64)
__device__ __forceinline__ void gemm16(const float4* A, const float4* B, int t, ull* c) {
    int a = t & 63, seg = t >> 6;                 // seg 0..3
    const float4* ap = A + a * AST4;
    const ull* Bu = reinterpret_cast<const ull*>(B);
    #pragma unroll
    for (int j4 = 0; j4 < 16; ++j4) {
        float4 av = ap[j4];
        #pragma unroll
        for (int jj = 0; jj < 4; ++jj) {
            float s = (jj == 0) ? av.x : (jj == 1) ? av.y : (jj == 2) ? av.z : av.w;
            ull ss = pk2(s, s);
            const ull* br = Bu + (j4 * 4 + jj) * 32 + seg * 8;   // row j, cols seg*16..
            #pragma unroll
            for (int k = 0; k < 8; ++k) ffma2(c[k], ss, br[k]);
        }
    }
}

// 512-thread GEMM: C[a][seg*8 .. +7], 8 accs (4 u64)
__device__ __forceinline__ void gemm8(const float4* A, const float4* B, int tid, float* out8) {
    int a = tid & 63, seg = tid >> 6;             // seg 0..7
    const float4* ap = A + a * AST4;
    const ull* Bu = reinterpret_cast<const ull*>(B);
    ull c0 = 0, c1 = 0, c2 = 0, c3 = 0;
    #pragma unroll
    for (int j4 = 0; j4 < 16; ++j4) {
        float4 av = ap[j4];
        #pragma unroll
        for (int jj = 0; jj < 4; ++jj) {
            float s = (jj == 0) ? av.x : (jj == 1) ? av.y : (jj == 2) ? av.z : av.w;
            ull ss = pk2(s, s);
            const ull* br = Bu + (j4 * 4 + jj) * 32 + seg * 4;   // cols seg*8..
            ffma2(c0, ss, br[0]);
            ffma2(c1, ss, br[1]);
            ffma2(c2, ss, br[2]);
            ffma2(c3, ss, br[3]);
        }
    }
    up2(c0, out8[0], out8[1]);
    up2(c1, out8[2], out8[3]);
    up2(c2, out8[4], out8[5]);
    up2(c3, out8[6], out8[7]);
}

// ---------------------------------------------------------------------------
// Fused quad kernel: CTA (t,v) computes Q = W_{4t}^{c0} W_{4t+1}^{c1} W_{4t+2}^{c2} W_{4t+3}^{c3}
// entirely in-CTA: build 4 W's from theta/u, two parallel 256-thread pair GEMMs,
// then a 512-thread combine GEMM -> bf16 g_Q4.
// blk 240..247: triple W60 W61 W62.
// grid = 248, block = 512, dynamic smem = SMEM_BYTES.
// ---------------------------------------------------------------------------
__global__ void __launch_bounds__(512) k_quadfused(const float* __restrict__ theta,
                                                   const float* __restrict__ u) {
    extern __shared__ float S[];
    float4* W0A = reinterpret_cast<float4*>(S + OFF_W0A);
    float4* W1B = reinterpret_cast<float4*>(S + OFF_W1B);
    float4* W2A = reinterpret_cast<float4*>(S + OFF_W2A);
    float4* W3B = reinterpret_cast<float4*>(S + OFF_W3B);
    float4* PaA = reinterpret_cast<float4*>(S + OFF_PAA);
    float4* PbB = reinterpret_cast<float4*>(S + OFF_PBB);
    float*  expa = S + OFF_EXPA;                 // [4][64]

    int blk = blockIdx.x, tid = threadIdx.x;
    int wid = tid >> 5, lane = tid & 31;
    const float4* th4 = reinterpret_cast<const float4*>(theta);

    if (blk < 240) {
        int t = blk >> 4, v = blk & 15;
        int i0 = 4 * t;
        if (wid < 4) warp_softmax(u, i0 + wid, expa + wid * 64, lane);
        __syncthreads();

        buildW_A(th4, i0 + 0, (v >> 3) & 1, expa,       W0A, tid);
        buildW_B(th4, i0 + 1, (v >> 2) & 1, expa + 64,  W1B, tid);
        buildW_A(th4, i0 + 2, (v >> 1) & 1, expa + 128, W2A, tid);
        buildW_B(th4, i0 + 3, (v     ) & 1, expa + 192, W3B, tid);
        __syncthreads();

        if (tid < 256) {
            ull c[8] = {0, 0, 0, 0, 0, 0, 0, 0};
            gemm16(W0A, W1B, tid, c);            // Pa = W0 @ W1, A-padded out
            int a = tid & 63, seg = tid >> 6;
            #pragma unroll
            for (int k = 0; k < 4; ++k) {
                float4 o;
                up2(c[2 * k],     o.x, o.y);
                up2(c[2 * k + 1], o.z, o.w);
                PaA[a * AST4 + seg * 4 + k] = o;
            }
        } else {
            ull c[8] = {0, 0, 0, 0, 0, 0, 0, 0};
            int t2 = tid - 256;
            gemm16(W2A, W3B, t2, c);             // Pb = W2 @ W3, B row-major out
            int a = t2 & 63, seg = t2 >> 6;
            #pragma unroll
            for (int k = 0; k < 4; ++k) {
                float4 o;
                up2(c[2 * k],     o.x, o.y);
                up2(c[2 * k + 1], o.z, o.w);
                PbB[a * 16 + seg * 4 + k] = o;
            }
        }
        __syncthreads();
    } else {
        int v = blk - 240;
        if (wid < 3) warp_softmax(u, 60 + wid, expa + wid * 64, lane);
        __syncthreads();

        buildW_A(th4, 60, (v >> 2) & 1, expa,       W0A, tid);
        buildW_B(th4, 61, (v >> 1) & 1, expa + 64,  W1B, tid);
        buildW_B(th4, 62, (v     ) & 1, expa + 128, PbB, tid);   // Pb := W62
        __syncthreads();

        if (tid < 256) {
            ull c[8] = {0, 0, 0, 0, 0, 0, 0, 0};
            gemm16(W0A, W1B, tid, c);            // Pa = W60 @ W61
            int a = tid & 63, seg = tid >> 6;
            #pragma unroll
            for (int k = 0; k < 4; ++k) {
                float4 o;
                up2(c[2 * k],     o.x, o.y);
                up2(c[2 * k + 1], o.z, o.w);
                PaA[a * AST4 + seg * 4 + k] = o;
            }
        }
        __syncthreads();
    }

    // combine: Q = Pa @ Pb, bf16 out
    float acc[8];
    gemm8(PaA, PbB, tid, acc);

    int a = tid & 63, seg = tid >> 6;
    __nv_bfloat162 p0 = __floats2bfloat162_rn(acc[0], acc[1]);
    __nv_bfloat162 p1 = __floats2bfloat162_rn(acc[2], acc[3]);
    __nv_bfloat162 p2 = __floats2bfloat162_rn(acc[4], acc[5]);
    __nv_bfloat162 p3 = __floats2bfloat162_rn(acc[6], acc[7]);
    uint4 uo;
    uo.x = *reinterpret_cast<unsigned*>(&p0);
    uo.y = *reinterpret_cast<unsigned*>(&p1);
    uo.z = *reinterpret_cast<unsigned*>(&p2);
    uo.w = *reinterpret_cast<unsigned*>(&p3);
    g_Q4[blk * 512 + seg * 64 + a] = uo;
}

// ---------------------------------------------------------------------------
// Kernel 2: per-batch stabilized log-semiring chain, 16 steps. (unchanged)
// ---------------------------------------------------------------------------
__device__ __forceinline__ int matq(unsigned long long bits, int t) {
    unsigned nib = (unsigned)(bits >> (4 * t)) & 0xFu;
    unsigned v = ((nib & 1u) << 3) | ((nib & 2u) << 1) | ((nib & 4u) >> 1) | ((nib & 8u) >> 3);
    return t * 16 + (int)v;
}

__device__ __forceinline__ float dotstep(const uint4* wr, const float4* e4) {
    float a0 = 0.f, a1 = 0.f, a2 = 0.f, a3 = 0.f;
    float a4 = 0.f, a5 = 0.f, a6 = 0.f, a7 = 0.f;
    #pragma unroll
    for (int q = 0; q < 8; ++q) {
        float4 e0 = e4[2 * q], e1 = e4[2 * q + 1];
        uint4 uw = wr[q];
        a0 = fmaf(__uint_as_float(uw.x << 16),          e0.x, a0);
        a1 = fmaf(__uint_as_float(uw.x & 0xffff0000u),  e0.y, a1);
        a2 = fmaf(__uint_as_float(uw.y << 16),          e0.z, a2);
        a3 = fmaf(__uint_as_float(uw.y & 0xffff0000u),  e0.w, a3);
        a4 = fmaf(__uint_as_float(uw.z << 16),          e1.x, a4);
        a5 = fmaf(__uint_as_float(uw.z & 0xffff0000u),  e1.y, a5);
        a6 = fmaf(__uint_as_float(uw.w << 16),          e1.z, a6);
        a7 = fmaf(__uint_as_float(uw.w & 0xffff0000u),  e1.w, a7);
    }
    return ((a0 + a1) + (a2 + a3)) + ((a4 + a5) + (a6 + a7));
}

__global__ void __launch_bounds__(64) k_main(const float* __restrict__ x,
                                             const float* __restrict__ theta,
                                             float* __restrict__ out) {
    int tid = threadIdx.x, w = tid >> 5, l = tid & 31;
    int b = blockIdx.x;

    __shared__ __align__(16) float se[2][64];
    __shared__ float red[2];
    __shared__ unsigned sbits[2];

    float xa = x[b * 64 + tid];
    unsigned bal = __ballot_sync(0xffffffffu, xa != 0.0f);
    if (l == 0) sbits[w] = bal;
    __syncthreads();
    unsigned long long bits =
        ((unsigned long long)sbits[1] << 32) | (unsigned long long)sbits[0];

    // v init: log p(x63 | a, col 0)
    int c63 = (int)(bits >> 63) & 1;
    float t63 = theta[63 * 4096 + tid * 64];
    float v = (c63 ? t63 : 0.0f) - fmaxf(t63, 0.0f)
            - __logf(1.0f + __expf(-fabsf(t63)));

    // prefetch step 0 (triple)
    int m0 = 240 + (((int)(bits >> 60) & 1) << 2)
                 + (((int)(bits >> 61) & 1) << 1)
                 +  ((int)(bits >> 62) & 1);
    uint4 wrA[8], wrB[8];
    {
        const uint4* base = g_Q4 + m0 * 512;
        #pragma unroll
        for (int q = 0; q < 8; ++q) wrA[q] = base[q * 64 + tid];
    }

    float m = 0.0f;
    #pragma unroll 1
    for (int sp = 0; sp < 8; ++sp) {
        // ---- even step: compute with wrA, prefetch wrB, refresh max ----
        {
            const uint4* nb = g_Q4 + matq(bits, 14 - 2 * sp) * 512;
            #pragma unroll
            for (int q = 0; q < 8; ++q) wrB[q] = nb[q * 64 + tid];

            float wm = v;
            #pragma unroll
            for (int o = 16; o; o >>= 1) wm = fmaxf(wm, __shfl_xor_sync(0xffffffffu, wm, o));
            if (l == 0) red[w] = wm;
            __syncthreads();
            m = fmaxf(red[0], red[1]);
            se[0][tid] = __expf(v - m);
            __syncthreads();
            v = __logf(dotstep(wrA, reinterpret_cast<const float4*>(se[0]))) + m;
        }
        // ---- odd step: compute with wrB, prefetch wrA, stale max ----
        {
            if (sp < 7) {
                const uint4* nb = g_Q4 + matq(bits, 13 - 2 * sp) * 512;
                #pragma unroll
                for (int q = 0; q < 8; ++q) wrA[q] = nb[q * 64 + tid];
            }
            se[1][tid] = __expf(v - m);
            __syncthreads();
            v = __logf(dotstep(wrB, reinterpret_cast<const float4*>(se[1]))) + m;
        }
    }

    out[b * 64 + tid] = v;
}

// ---------------------------------------------------------------------------
extern "C" void kernel_launch(void* const* d_in, const int* in_sizes, int n_in,
                              void* d_out, int out_size) {
    const float* x     = nullptr;
    const float* theta = nullptr;
    const float* u     = nullptr;
    for (int i = 0; i < n_in; ++i) {
        if      (in_sizes[i] == BATCH * NIN)       x     = (const float*)d_in[i];
        else if (in_sizes[i] == NIN * ADIM * ADIM) theta = (const float*)d_in[i];
        else if (in_sizes[i] == (NIN - 1) * ADIM)  u     = (const float*)d_in[i];
    }

    static bool attr_done = false;
    if (!attr_done) {
        cudaFuncSetAttribute(k_quadfused,
                             cudaFuncAttributeMaxDynamicSharedMemorySize, SMEM_BYTES);
        attr_done = true;
    }

    k_quadfused<<<248, 512, SMEM_BYTES>>>(theta, u);
    k_main<<<BATCH, 64>>>(x, theta, (float*)d_out);
}

// round 10
// speedup vs baseline: 1.2347x; 1.2347x over previous
#include <cuda_runtime.h>
#include <cuda_bf16.h>

#define BATCH 512
#define NIN   64
#define ADIM  64

typedef unsigned long long ull;

// ---------------- device scratch (static, no allocation) -------------------
__device__ float4 g_P4[31 * 4 * 1024];   // pair products, row-major fp32 [mat][a*16+q]
__device__ float4 g_Qf[248 * 1024];      // quads(240)+triples(8), fp32, chunk layout:
                                         //   mat*1024 + q*64 + row ; float4 = row's k=4q..4q+3

#define AST4 17                          // A row stride in float4 units (68 floats)

// ---- packed f32x2 helpers (sm_103a) ---------------------------------------
__device__ __forceinline__ void ffma2(ull& d, ull a, ull b) {
    asm("fma.rn.f32x2 %0, %1, %2, %0;" : "+l"(d) : "l"(a), "l"(b));
}
__device__ __forceinline__ ull pk2(float x, float y) {
    ull r; asm("mov.b64 %0, {%1, %2};" : "=l"(r) : "f"(x), "f"(y)); return r;
}
__device__ __forceinline__ void up2(ull v, float& x, float& y) {
    asm("mov.b64 {%0, %1}, %2;" : "=f"(x), "=f"(y) : "l"(v));
}

// 64x64x64 GEMM consumer: A in padded-f4 smem (stride AST4), B row-major f4.
// thread = (a = tid&63, seg = tid>>6); computes C[a][seg*8 .. +7].
__device__ __forceinline__ void gemm_inner(const float4* sA4, const float4* sB4,
                                           int a, int seg, float* out8) {
    ull c0 = 0, c1 = 0, c2 = 0, c3 = 0;
    const float4* ap = sA4 + a * AST4;
    const ull*    bp = reinterpret_cast<const ull*>(sB4 + seg * 2);
    #pragma unroll
    for (int j4 = 0; j4 < 16; ++j4) {
        float4 av = ap[j4];
        #pragma unroll
        for (int jj = 0; jj < 4; ++jj) {
            float s = (jj == 0) ? av.x : (jj == 1) ? av.y : (jj == 2) ? av.z : av.w;
            ull ss = pk2(s, s);
            const ull* br = bp + (j4 * 4 + jj) * 32;   // 16 f4 per row = 32 u64
            ffma2(c0, ss, br[0]);
            ffma2(c1, ss, br[1]);
            ffma2(c2, ss, br[2]);
            ffma2(c3, ss, br[3]);
        }
    }
    up2(c0, out8[0], out8[1]);
    up2(c1, out8[2], out8[3]);
    up2(c2, out8[4], out8[5]);
    up2(c3, out8[6], out8[7]);
}

// ---------------------------------------------------------------------------
// Kernel 1: fused prep+pair. CTA (t,vv): A=W_{2t}^{c0}, B=W_{2t+1}^{c1} inline
// from theta/u, then P = A@B. grid=124, block=512.
// W_i^c[a,k] = sigmoid_c(theta[i,a,k]) * softmax(u[i])[k]
// ---------------------------------------------------------------------------
__global__ void __launch_bounds__(512) k_pair(const float* __restrict__ theta,
                                              const float* __restrict__ u) {
    __shared__ __align__(16) float sA[64 * AST4 * 4];
    __shared__ __align__(16) float sB[4096];
    __shared__ float expa[2][64];

    int blk = blockIdx.x, tid = threadIdx.x;
    int t = blk >> 2, vv = blk & 3;
    int i0 = 2 * t, i1 = 2 * t + 1, c0 = vv >> 1, c1 = vv & 1;
    int wid = tid >> 5, lane = tid & 31;

    if (wid < 2) {                               // softmax(u[i0]), softmax(u[i1])
        int i = i0 + wid;
        float u0 = u[i * 64 + lane], u1 = u[i * 64 + 32 + lane];
        float mm = fmaxf(u0, u1);
        #pragma unroll
        for (int o = 16; o; o >>= 1) mm = fmaxf(mm, __shfl_xor_sync(0xffffffffu, mm, o));
        float ss = __expf(u0 - mm) + __expf(u1 - mm);
        #pragma unroll
        for (int o = 16; o; o >>= 1) ss += __shfl_xor_sync(0xffffffffu, ss, o);
        float lse = mm + __logf(ss);
        expa[wid][lane]      = __expf(u0 - lse);
        expa[wid][lane + 32] = __expf(u1 - lse);
    }
    __syncthreads();

    const float4* th4 = reinterpret_cast<const float4*>(theta);
    float4* sA4 = reinterpret_cast<float4*>(sA);
    float4* sB4 = reinterpret_cast<float4*>(sB);
    #pragma unroll
    for (int r = 0; r < 2; ++r) {
        int idx4 = tid + 512 * r;                // float4 index 0..1023
        int row = idx4 >> 4, q = idx4 & 15;
        int k0 = q * 4;
        float4 ta = th4[i0 * 1024 + idx4];
        float4 oa;
        { float s = __fdividef(1.0f, 1.0f + __expf(-ta.x)); oa.x = (c0 ? s : 1.0f - s) * expa[0][k0 + 0]; }
        { float s = __fdividef(1.0f, 1.0f + __expf(-ta.y)); oa.y = (c0 ? s : 1.0f - s) * expa[0][k0 + 1]; }
        { float s = __fdividef(1.0f, 1.0f + __expf(-ta.z)); oa.z = (c0 ? s : 1.0f - s) * expa[0][k0 + 2]; }
        { float s = __fdividef(1.0f, 1.0f + __expf(-ta.w)); oa.w = (c0 ? s : 1.0f - s) * expa[0][k0 + 3]; }
        sA4[row * AST4 + q] = oa;
        float4 tb = th4[i1 * 1024 + idx4];
        float4 ob;
        { float s = __fdividef(1.0f, 1.0f + __expf(-tb.x)); ob.x = (c1 ? s : 1.0f - s) * expa[1][k0 + 0]; }
        { float s = __fdividef(1.0f, 1.0f + __expf(-tb.y)); ob.y = (c1 ? s : 1.0f - s) * expa[1][k0 + 1]; }
        { float s = __fdividef(1.0f, 1.0f + __expf(-tb.z)); ob.z = (c1 ? s : 1.0f - s) * expa[1][k0 + 2]; }
        { float s = __fdividef(1.0f, 1.0f + __expf(-tb.w)); ob.w = (c1 ? s : 1.0f - s) * expa[1][k0 + 3]; }
        sB4[idx4] = ob;
    }
    __syncthreads();

    int a = tid & 63, seg = tid >> 6;
    float acc[8];
    gemm_inner(sA4, sB4, a, seg, acc);

    float4* C4 = g_P4 + blk * 1024;
    C4[a * 16 + seg * 2]     = make_float4(acc[0], acc[1], acc[2], acc[3]);
    C4[a * 16 + seg * 2 + 1] = make_float4(acc[4], acc[5], acc[6], acc[7]);
}

// ---------------------------------------------------------------------------
// Kernel 2: quads Q = P_{2t}^{v>>2} @ P_{2t+1}^{v&3} (blk<240);
//           triples T = P_30^{v>>1} @ W62^{v&1} (blk 240..247, W62 inline).
// Output fp32 chunk layout for k_main. grid=248, block=512.
// ---------------------------------------------------------------------------
__global__ void __launch_bounds__(512) k_quad(const float* __restrict__ theta,
                                              const float* __restrict__ u) {
    __shared__ __align__(16) float sA[64 * AST4 * 4];
    __shared__ __align__(16) float sB[4096];
    __shared__ float expa[64];
    int blk = blockIdx.x, tid = threadIdx.x;

    float4* sA4 = reinterpret_cast<float4*>(sA);
    float4* sB4 = reinterpret_cast<float4*>(sB);

    if (blk < 240) {
        int t = blk >> 4, v = blk & 15;
        const float4* A4 = g_P4 + ((2 * t)     * 4 + (v >> 2)) * 1024;
        const float4* B4 = g_P4 + ((2 * t + 1) * 4 + (v & 3))  * 1024;
        #pragma unroll
        for (int r = 0; r < 2; ++r) {
            int idx4 = tid + 512 * r;            // = row*16 + q
            int row = idx4 >> 4, q = idx4 & 15;
            sA4[row * AST4 + q] = A4[idx4];
            sB4[idx4] = B4[idx4];
        }
    } else {
        int v = blk - 240;
        const float4* A4 = g_P4 + (30 * 4 + (v >> 1)) * 1024;
        #pragma unroll
        for (int r = 0; r < 2; ++r) {
            int idx4 = tid + 512 * r;
            int row = idx4 >> 4, q = idx4 & 15;
            sA4[row * AST4 + q] = A4[idx4];
        }
        int c = v & 1;
        if (tid < 32) {                          // softmax(u[62])
            float u0 = u[62 * 64 + tid], u1 = u[62 * 64 + 32 + tid];
            float mm = fmaxf(u0, u1);
            #pragma unroll
            for (int o = 16; o; o >>= 1) mm = fmaxf(mm, __shfl_xor_sync(0xffffffffu, mm, o));
            float ss = __expf(u0 - mm) + __expf(u1 - mm);
            #pragma unroll
            for (int o = 16; o; o >>= 1) ss += __shfl_xor_sync(0xffffffffu, ss, o);
            float lse = mm + __logf(ss);
            expa[tid]      = __expf(u0 - lse);
            expa[tid + 32] = __expf(u1 - lse);
        }
        __syncthreads();
        const float4* th4 = reinterpret_cast<const float4*>(theta);
        #pragma unroll
        for (int r = 0; r < 2; ++r) {
            int idx4 = tid + 512 * r;
            int k0 = (idx4 * 4) & 63;
            float4 tb = th4[62 * 1024 + idx4];
            float4 ob;
            { float s = __fdividef(1.0f, 1.0f + __expf(-tb.x)); ob.x = (c ? s : 1.0f - s) * expa[k0 + 0]; }
            { float s = __fdividef(1.0f, 1.0f + __expf(-tb.y)); ob.y = (c ? s : 1.0f - s) * expa[k0 + 1]; }
            { float s = __fdividef(1.0f, 1.0f + __expf(-tb.z)); ob.z = (c ? s : 1.0f - s) * expa[k0 + 2]; }
            { float s = __fdividef(1.0f, 1.0f + __expf(-tb.w)); ob.w = (c ? s : 1.0f - s) * expa[k0 + 3]; }
            sB4[idx4] = ob;
        }
    }
    __syncthreads();

    int a = tid & 63, seg = tid >> 6;
    float acc[8];
    gemm_inner(sA4, sB4, a, seg, acc);

    // fp32 chunk-transposed output: chunk q (4 k's) at [q*64 + row]
    g_Qf[blk * 1024 + (seg * 2)     * 64 + a] = make_float4(acc[0], acc[1], acc[2], acc[3]);
    g_Qf[blk * 1024 + (seg * 2 + 1) * 64 + a] = make_float4(acc[4], acc[5], acc[6], acc[7]);
}

// ---------------------------------------------------------------------------
// Kernel 3: per-batch stabilized log-semiring chain, 16 steps, fp32 weights.
// CTA = 64 threads = 1 batch, thread = row. One __syncthreads per step.
// Consumption order: step 0 = triple m0; even sp>0 -> t = 15-2sp; odd sp -> t = 14-2sp
// (t = 14,13,...,0 overall). grid = 512, block = 64.
// ---------------------------------------------------------------------------
__device__ __forceinline__ int matq(unsigned long long bits, int t) {
    unsigned nib = (unsigned)(bits >> (4 * t)) & 0xFu;
    unsigned v = ((nib & 1u) << 3) | ((nib & 2u) << 1) | ((nib & 4u) >> 1) | ((nib & 8u) >> 3);
    return t * 16 + (int)v;
}

// dot over 64 k's, fp32 weights in wr[16] (chunk q = k 4q..4q+3), se in smem.
// lo = sum over k<32 (q<8), hi = sum over k>=32.
__device__ __forceinline__ void dotf(const float4* wr, const float4* e4,
                                     float& lo, float& hi) {
    float c0 = 0.f, c1 = 0.f, c2 = 0.f, c3 = 0.f;
    float d0 = 0.f, d1 = 0.f, d2 = 0.f, d3 = 0.f;
    #pragma unroll
    for (int q = 0; q < 8; ++q) {
        float4 w = wr[q], e = e4[q];
        c0 = fmaf(w.x, e.x, c0);
        c1 = fmaf(w.y, e.y, c1);
        c2 = fmaf(w.z, e.z, c2);
        c3 = fmaf(w.w, e.w, c3);
    }
    #pragma unroll
    for (int q = 8; q < 16; ++q) {
        float4 w = wr[q], e = e4[q];
        d0 = fmaf(w.x, e.x, d0);
        d1 = fmaf(w.y, e.y, d1);
        d2 = fmaf(w.z, e.z, d2);
        d3 = fmaf(w.w, e.w, d3);
    }
    lo = (c0 + c1) + (c2 + c3);
    hi = (d0 + d1) + (d2 + d3);
}

__global__ void __launch_bounds__(64) k_main(const float* __restrict__ x,
                                             const float* __restrict__ theta,
                                             float* __restrict__ out) {
    int tid = threadIdx.x, w = tid >> 5, l = tid & 31;
    int b = blockIdx.x;

    __shared__ __align__(16) float se[2][64];
    __shared__ float red[2];
    __shared__ unsigned sbits[2];

    float xa = x[b * 64 + tid];
    unsigned bal = __ballot_sync(0xffffffffu, xa != 0.0f);
    if (l == 0) sbits[w] = bal;
    __syncthreads();
    unsigned long long bits =
        ((unsigned long long)sbits[1] << 32) | (unsigned long long)sbits[0];

    // v init: log p(x63 | a, col 0)
    int c63 = (int)(bits >> 63) & 1;
    float t63 = theta[63 * 4096 + tid * 64];
    float v = (c63 ? t63 : 0.0f) - fmaxf(t63, 0.0f)
            - __logf(1.0f + __expf(-fabsf(t63)));

    int m0 = 240 + (((int)(bits >> 60) & 1) << 2)
                 + (((int)(bits >> 61) & 1) << 1)
                 +  ((int)(bits >> 62) & 1);

    float m = 0.0f;
    float4 wr[16];

    #pragma unroll 1
    for (int sp = 0; sp < 8; ++sp) {
        // ---- even step (s=2sp): refresh max (warp-local scaling, 1 sync) ----
        {
            int mat = (sp == 0) ? m0 : matq(bits, 15 - 2 * sp);   // t=13,11,...,1
            const float4* base = g_Qf + mat * 1024;
            #pragma unroll
            for (int q = 0; q < 16; ++q) wr[q] = base[q * 64 + tid];  // issue early

            float wm = v;
            #pragma unroll
            for (int o = 16; o; o >>= 1) wm = fmaxf(wm, __shfl_xor_sync(0xffffffffu, wm, o));
            if (l == 0) red[w] = wm;
            se[0][tid] = __expf(v - wm);          // warp-local scale
            __syncthreads();
            m = fmaxf(red[0], red[1]);
            float s0 = __expf(red[0] - m);
            float s1 = __expf(red[1] - m);
            float lo, hi;
            dotf(wr, reinterpret_cast<const float4*>(se[0]), lo, hi);
            v = __logf(fmaf(s0, lo, s1 * hi)) + m;
        }
        // ---- odd step (s=2sp+1): stale max, 1 sync ----
        {
            int mat = matq(bits, 14 - 2 * sp);    // t=14,12,...,0
            const float4* base = g_Qf + mat * 1024;
            #pragma unroll
            for (int q = 0; q < 16; ++q) wr[q] = base[q * 64 + tid];

            se[1][tid] = __expf(v - m);
            __syncthreads();
            float lo, hi;
            dotf(wr, reinterpret_cast<const float4*>(se[1]), lo, hi);
            v = __logf(lo + hi) + m;
        }
    }

    out[b * 64 + tid] = v;
}

// ---------------------------------------------------------------------------
extern "C" void kernel_launch(void* const* d_in, const int* in_sizes, int n_in,
                              void* d_out, int out_size) {
    const float* x     = nullptr;
    const float* theta = nullptr;
    const float* u     = nullptr;
    for (int i = 0; i < n_in; ++i) {
        if      (in_sizes[i] == BATCH * NIN)       x     = (const float*)d_in[i];
        else if (in_sizes[i] == NIN * ADIM * ADIM) theta = (const float*)d_in[i];
        else if (in_sizes[i] == (NIN - 1) * ADIM)  u     = (const float*)d_in[i];
    }

    k_pair<<<124, 512>>>(theta, u);
    k_quad<<<248, 512>>>(theta, u);
    k_main<<<BATCH, 64>>>(x, theta, (float*)d_out);
}

// round 11
// speedup vs baseline: 1.2376x; 1.0024x over previous
#include <cuda_runtime.h>
#include <cuda_bf16.h>

#define BATCH 512
#define NIN   64
#define ADIM  64

typedef unsigned long long ull;

// ---------------- device scratch (static, no allocation) -------------------
__device__ float4 g_P4[31 * 4 * 1024];   // pair products, row-major fp32 [mat][a*16+q]
__device__ uint4  g_Q4[248 * 512];       // quads(240)+triples(8), bf16, chunk layout:
                                         //   mat*512 + q*64 + row ; uint4 = row's k=8q..8q+7

#define AST4 17                          // A row stride in float4 units (68 floats)

// ---- packed f32x2 helpers (sm_103a) ---------------------------------------
__device__ __forceinline__ void ffma2(ull& d, ull a, ull b) {
    asm("fma.rn.f32x2 %0, %1, %2, %0;" : "+l"(d) : "l"(a), "l"(b));
}
__device__ __forceinline__ ull pk2(float x, float y) {
    ull r; asm("mov.b64 %0, {%1, %2};" : "=l"(r) : "f"(x), "f"(y)); return r;
}
__device__ __forceinline__ void up2(ull v, float& x, float& y) {
    asm("mov.b64 {%0, %1}, %2;" : "=f"(x), "=f"(y) : "l"(v));
}

// 1024-thread 64x64x64 GEMM: thread = (a = tid&63, seg = tid>>6, 0..15),
// computes C[a][seg*4 .. +3]. A padded-f4 smem (stride AST4), B row-major f4.
__device__ __forceinline__ void gemm_inner(const float4* sA4, const float4* sB4,
                                           int a, int seg, float* out4) {
    ull c0 = 0, c1 = 0;
    const float4* ap = sA4 + a * AST4;
    const ull*    bp = reinterpret_cast<const ull*>(sB4 + seg);
    #pragma unroll
    for (int j4 = 0; j4 < 16; ++j4) {
        float4 av = ap[j4];
        #pragma unroll
        for (int jj = 0; jj < 4; ++jj) {
            float s = (jj == 0) ? av.x : (jj == 1) ? av.y : (jj == 2) ? av.z : av.w;
            ull ss = pk2(s, s);
            const ull* br = bp + (j4 * 4 + jj) * 32;   // row j, cols seg*4..
            ffma2(c0, ss, br[0]);
            ffma2(c1, ss, br[1]);
        }
    }
    up2(c0, out4[0], out4[1]);
    up2(c1, out4[2], out4[3]);
}

__device__ __forceinline__ float sigc(float t, int c) {
    float s = __fdividef(1.0f, 1.0f + __expf(-t));
    return c ? s : 1.0f - s;
}

// ---------------------------------------------------------------------------
// Kernel 1: fused prep+pair. CTA (t,vv): A=W_{2t}^{c0}, B=W_{2t+1}^{c1} inline
// from theta/u, then P = A@B. grid=124, block=1024.
// ---------------------------------------------------------------------------
__global__ void __launch_bounds__(1024) k_pair(const float* __restrict__ theta,
                                               const float* __restrict__ u) {
    __shared__ __align__(16) float sA[64 * AST4 * 4];
    __shared__ __align__(16) float sB[4096];
    __shared__ float expa[2][64];

    int blk = blockIdx.x, tid = threadIdx.x;
    int t = blk >> 2, vv = blk & 3;
    int i0 = 2 * t, i1 = 2 * t + 1, c0 = vv >> 1, c1 = vv & 1;
    int wid = tid >> 5, lane = tid & 31;

    if (wid < 2) {                               // softmax(u[i0]), softmax(u[i1])
        int i = i0 + wid;
        float u0 = u[i * 64 + lane], u1 = u[i * 64 + 32 + lane];
        float mm = fmaxf(u0, u1);
        #pragma unroll
        for (int o = 16; o; o >>= 1) mm = fmaxf(mm, __shfl_xor_sync(0xffffffffu, mm, o));
        float ss = __expf(u0 - mm) + __expf(u1 - mm);
        #pragma unroll
        for (int o = 16; o; o >>= 1) ss += __shfl_xor_sync(0xffffffffu, ss, o);
        float lse = mm + __logf(ss);
        expa[wid][lane]      = __expf(u0 - lse);
        expa[wid][lane + 32] = __expf(u1 - lse);
    }
    __syncthreads();

    const float4* th4 = reinterpret_cast<const float4*>(theta);
    float4* sA4 = reinterpret_cast<float4*>(sA);
    float4* sB4 = reinterpret_cast<float4*>(sB);
    {
        int idx4 = tid;                          // one float4 of A and of B per thread
        int row = idx4 >> 4, q = idx4 & 15, k0 = q * 4;
        float4 ta = th4[i0 * 1024 + idx4];
        float4 oa;
        oa.x = sigc(ta.x, c0) * expa[0][k0 + 0];
        oa.y = sigc(ta.y, c0) * expa[0][k0 + 1];
        oa.z = sigc(ta.z, c0) * expa[0][k0 + 2];
        oa.w = sigc(ta.w, c0) * expa[0][k0 + 3];
        sA4[row * AST4 + q] = oa;
        float4 tb = th4[i1 * 1024 + idx4];
        float4 ob;
        ob.x = sigc(tb.x, c1) * expa[1][k0 + 0];
        ob.y = sigc(tb.y, c1) * expa[1][k0 + 1];
        ob.z = sigc(tb.z, c1) * expa[1][k0 + 2];
        ob.w = sigc(tb.w, c1) * expa[1][k0 + 3];
        sB4[idx4] = ob;
    }
    __syncthreads();

    int a = tid & 63, seg = tid >> 6;
    float acc[4];
    gemm_inner(sA4, sB4, a, seg, acc);

    g_P4[blk * 1024 + a * 16 + seg] = make_float4(acc[0], acc[1], acc[2], acc[3]);
}

// ---------------------------------------------------------------------------
// Kernel 2: quads Q = P_{2t}^{v>>2} @ P_{2t+1}^{v&3} (blk<240);
//           triples T = P_30^{v>>1} @ W62^{v&1} (blk 240..247, W62 inline).
// Output bf16 chunk layout for k_main. grid=248, block=1024.
// ---------------------------------------------------------------------------
__global__ void __launch_bounds__(1024) k_quad(const float* __restrict__ theta,
                                               const float* __restrict__ u) {
    __shared__ __align__(16) float sA[64 * AST4 * 4];
    __shared__ __align__(16) float sB[4096];
    __shared__ float expa[64];
    int blk = blockIdx.x, tid = threadIdx.x;

    float4* sA4 = reinterpret_cast<float4*>(sA);
    float4* sB4 = reinterpret_cast<float4*>(sB);

    if (blk < 240) {
        int t = blk >> 4, v = blk & 15;
        const float4* A4 = g_P4 + ((2 * t)     * 4 + (v >> 2)) * 1024;
        const float4* B4 = g_P4 + ((2 * t + 1) * 4 + (v & 3))  * 1024;
        int idx4 = tid;
        int row = idx4 >> 4, q = idx4 & 15;
        sA4[row * AST4 + q] = A4[idx4];
        sB4[idx4] = B4[idx4];
    } else {
        int v = blk - 240;
        const float4* A4 = g_P4 + (30 * 4 + (v >> 1)) * 1024;
        {
            int idx4 = tid;
            int row = idx4 >> 4, q = idx4 & 15;
            sA4[row * AST4 + q] = A4[idx4];
        }
        int c = v & 1;
        if (tid < 32) {                          // softmax(u[62])
            float u0 = u[62 * 64 + tid], u1 = u[62 * 64 + 32 + tid];
            float mm = fmaxf(u0, u1);
            #pragma unroll
            for (int o = 16; o; o >>= 1) mm = fmaxf(mm, __shfl_xor_sync(0xffffffffu, mm, o));
            float ss = __expf(u0 - mm) + __expf(u1 - mm);
            #pragma unroll
            for (int o = 16; o; o >>= 1) ss += __shfl_xor_sync(0xffffffffu, ss, o);
            float lse = mm + __logf(ss);
            expa[tid]      = __expf(u0 - lse);
            expa[tid + 32] = __expf(u1 - lse);
        }
        __syncthreads();
        const float4* th4 = reinterpret_cast<const float4*>(theta);
        {
            int idx4 = tid;
            int k0 = (idx4 * 4) & 63;
            float4 tb = th4[62 * 1024 + idx4];
            float4 ob;
            ob.x = sigc(tb.x, c) * expa[k0 + 0];
            ob.y = sigc(tb.y, c) * expa[k0 + 1];
            ob.z = sigc(tb.z, c) * expa[k0 + 2];
            ob.w = sigc(tb.w, c) * expa[k0 + 3];
            sB4[idx4] = ob;
        }
    }
    __syncthreads();

    int a = tid & 63, seg = tid >> 6;
    float acc[4];
    gemm_inner(sA4, sB4, a, seg, acc);

    // bf16 chunk layout: uint4 chunk q = seg>>1 holds k=8q..8q+7; this thread
    // writes the (seg&1) half (4 k's) as uint2.
    __nv_bfloat162 p0 = __floats2bfloat162_rn(acc[0], acc[1]);
    __nv_bfloat162 p1 = __floats2bfloat162_rn(acc[2], acc[3]);
    uint2 uo;
    uo.x = *reinterpret_cast<unsigned*>(&p0);
    uo.y = *reinterpret_cast<unsigned*>(&p1);
    uint2* D = reinterpret_cast<uint2*>(g_Q4);
    D[(blk * 512 + (seg >> 1) * 64 + a) * 2 + (seg & 1)] = uo;
}

// ---------------------------------------------------------------------------
// Kernel 3: per-batch stabilized log-semiring chain, 16 steps, bf16 weights,
// single __syncthreads per step (warp-local exp scaling on even steps).
// Step 0 = triple m0; even sp>0 -> t = 15-2sp; odd sp -> t = 14-2sp.
// grid = 512, block = 64.
// ---------------------------------------------------------------------------
__device__ __forceinline__ int matq(unsigned long long bits, int t) {
    unsigned nib = (unsigned)(bits >> (4 * t)) & 0xFu;
    unsigned v = ((nib & 1u) << 3) | ((nib & 2u) << 1) | ((nib & 4u) >> 1) | ((nib & 8u) >> 3);
    return t * 16 + (int)v;
}

// bf16 dot, split: lo = k<32 (chunks 0..3), hi = k>=32 (chunks 4..7)
__device__ __forceinline__ void dotb(const uint4* wr, const float4* e4,
                                     float& lo, float& hi) {
    float a0 = 0.f, a1 = 0.f, a2 = 0.f, a3 = 0.f;
    float b0 = 0.f, b1 = 0.f, b2 = 0.f, b3 = 0.f;
    #pragma unroll
    for (int q = 0; q < 4; ++q) {
        float4 e0 = e4[2 * q], e1 = e4[2 * q + 1];
        uint4 uw = wr[q];
        a0 = fmaf(__uint_as_float(uw.x << 16),          e0.x, a0);
        a1 = fmaf(__uint_as_float(uw.x & 0xffff0000u),  e0.y, a1);
        a2 = fmaf(__uint_as_float(uw.y << 16),          e0.z, a2);
        a3 = fmaf(__uint_as_float(uw.y & 0xffff0000u),  e0.w, a3);
        a0 = fmaf(__uint_as_float(uw.z << 16),          e1.x, a0);
        a1 = fmaf(__uint_as_float(uw.z & 0xffff0000u),  e1.y, a1);
        a2 = fmaf(__uint_as_float(uw.w << 16),          e1.z, a2);
        a3 = fmaf(__uint_as_float(uw.w & 0xffff0000u),  e1.w, a3);
    }
    #pragma unroll
    for (int q = 4; q < 8; ++q) {
        float4 e0 = e4[2 * q], e1 = e4[2 * q + 1];
        uint4 uw = wr[q];
        b0 = fmaf(__uint_as_float(uw.x << 16),          e0.x, b0);
        b1 = fmaf(__uint_as_float(uw.x & 0xffff0000u),  e0.y, b1);
        b2 = fmaf(__uint_as_float(uw.y << 16),          e0.z, b2);
        b3 = fmaf(__uint_as_float(uw.y & 0xffff0000u),  e0.w, b3);
        b0 = fmaf(__uint_as_float(uw.z << 16),          e1.x, b0);
        b1 = fmaf(__uint_as_float(uw.z & 0xffff0000u),  e1.y, b1);
        b2 = fmaf(__uint_as_float(uw.w << 16),          e1.z, b2);
        b3 = fmaf(__uint_as_float(uw.w & 0xffff0000u),  e1.w, b3);
    }
    lo = (a0 + a1) + (a2 + a3);
    hi = (b0 + b1) + (b2 + b3);
}

__global__ void __launch_bounds__(64) k_main(const float* __restrict__ x,
                                             const float* __restrict__ theta,
                                             float* __restrict__ out) {
    int tid = threadIdx.x, w = tid >> 5, l = tid & 31;
    int b = blockIdx.x;

    __shared__ __align__(16) float se[2][64];
    __shared__ float red[2];
    __shared__ unsigned sbits[2];

    float xa = x[b * 64 + tid];
    unsigned bal = __ballot_sync(0xffffffffu, xa != 0.0f);
    if (l == 0) sbits[w] = bal;
    __syncthreads();
    unsigned long long bits =
        ((unsigned long long)sbits[1] << 32) | (unsigned long long)sbits[0];

    // v init: log p(x63 | a, col 0)
    int c63 = (int)(bits >> 63) & 1;
    float t63 = theta[63 * 4096 + tid * 64];
    float v = (c63 ? t63 : 0.0f) - fmaxf(t63, 0.0f)
            - __logf(1.0f + __expf(-fabsf(t63)));

    int m0 = 240 + (((int)(bits >> 60) & 1) << 2)
                 + (((int)(bits >> 61) & 1) << 1)
                 +  ((int)(bits >> 62) & 1);

    float m = 0.0f;
    uint4 wr[8];

    #pragma unroll 1
    for (int sp = 0; sp < 8; ++sp) {
        // ---- even step: refresh max (warp-local scaling), 1 sync ----
        {
            int mat = (sp == 0) ? m0 : matq(bits, 15 - 2 * sp);   // t=13,11,...,1
            const uint4* base = g_Q4 + mat * 512;
            #pragma unroll
            for (int q = 0; q < 8; ++q) wr[q] = base[q * 64 + tid];  // issue early

            float wm = v;
            #pragma unroll
            for (int o = 16; o; o >>= 1) wm = fmaxf(wm, __shfl_xor_sync(0xffffffffu, wm, o));
            if (l == 0) red[w] = wm;
            se[0][tid] = __expf(v - wm);          // warp-local scale
            __syncthreads();
            m = fmaxf(red[0], red[1]);
            float s0 = __expf(red[0] - m);
            float s1 = __expf(red[1] - m);
            float lo, hi;
            dotb(wr, reinterpret_cast<const float4*>(se[0]), lo, hi);
            v = __logf(fmaf(s0, lo, s1 * hi)) + m;
        }
        // ---- odd step: stale max, 1 sync ----
        {
            int mat = matq(bits, 14 - 2 * sp);    // t=14,12,...,0
            const uint4* base = g_Q4 + mat * 512;
            #pragma unroll
            for (int q = 0; q < 8; ++q) wr[q] = base[q * 64 + tid];

            se[1][tid] = __expf(v - m);
            __syncthreads();
            float lo, hi;
            dotb(wr, reinterpret_cast<const float4*>(se[1]), lo, hi);
            v = __logf(lo + hi) + m;
        }
    }

    out[b * 64 + tid] = v;
}

// ---------------------------------------------------------------------------
extern "C" void kernel_launch(void* const* d_in, const int* in_sizes, int n_in,
                              void* d_out, int out_size) {
    const float* x     = nullptr;
    const float* theta = nullptr;
    const float* u     = nullptr;
    for (int i = 0; i < n_in; ++i) {
        if      (in_sizes[i] == BATCH * NIN)       x     = (const float*)d_in[i];
        else if (in_sizes[i] == NIN * ADIM * ADIM) theta = (const float*)d_in[i];
        else if (in_sizes[i] == (NIN - 1) * ADIM)  u     = (const float*)d_in[i];
    }

    k_pair<<<124, 1024>>>(theta, u);
    k_quad<<<248, 1024>>>(theta, u);
    k_main<<<BATCH, 64>>>(x, theta, (float*)d_out);
}